// round 17
// baseline (speedup 1.0000x reference)
#include <cuda_runtime.h>
#include <cstdint>
#include <cstddef>

typedef unsigned long long ull;

#define DEV_INLINE __device__ __forceinline__

DEV_INLINE ull fma2(ull a, ull b, ull c) {
    ull d; asm("fma.rn.f32x2 %0, %1, %2, %3;" : "=l"(d) : "l"(a), "l"(b), "l"(c)); return d;
}
DEV_INLINE float2 unpk(ull v) {
    float2 f; asm("mov.b64 {%0, %1}, %2;" : "=f"(f.x), "=f"(f.y) : "l"(v)); return f;
}
DEV_INLINE unsigned tf32_(float x) {
    unsigned r; asm("cvt.rna.tf32.f32 %0, %1;" : "=r"(r) : "f"(x)); return r;
}
DEV_INLINE void mma_tf32(float* c, const unsigned* a, unsigned b0, unsigned b1) {
    asm("mma.sync.aligned.m16n8k8.row.col.f32.tf32.tf32.f32 "
        "{%0,%1,%2,%3}, {%4,%5,%6,%7}, {%8,%9}, {%0,%1,%2,%3};"
        : "+f"(c[0]), "+f"(c[1]), "+f"(c[2]), "+f"(c[3])
        : "r"(a[0]), "r"(a[1]), "r"(a[2]), "r"(a[3]), "r"(b0), "r"(b1));
}
DEV_INLINE float sigm_(float x) { float e = __expf(-x); return __fdividef(1.f, 1.f + e); }
DEV_INLINE float tanh_(float a) { float t = __expf(-2.f * a); return __fdividef(1.f - t, 1.f + t); }

#define BB 256
#define TT 512
#define HH 256
#define G3 768

__device__ float g_xg[(size_t)BB * TT * G3];
__device__ float g_out0[(size_t)BB * TT * HH];
__device__ float g_hT[BB * HH];

// ---------------------------------------------------------------------------
// tf32 tensor-core GEMM: register prefetch + 2-stage smem double buffer (R16).
// ---------------------------------------------------------------------------
#define TSTR 136
#define GEMM_SMEM (2 * 2 * 16 * TSTR * 4)

__global__ __launch_bounds__(256, 2) void gemm_tf32(
    const float* __restrict__ A, const float* __restrict__ W,
    const float* __restrict__ bias, float* __restrict__ C,
    int M, int N, int Kiter, int Ksrc)
{
    extern __shared__ unsigned gsm[];
    unsigned* Asb = gsm;
    unsigned* Bsb = gsm + 2 * 16 * TSTR;

    const int tid = threadIdx.x;
    const int lane = tid & 31;
    const int wid = tid >> 5;
    const int wm = wid & 1;
    const int wn = wid >> 1;
    const int g  = lane >> 2;
    const int tg = lane & 3;
    const int mb = blockIdx.x * 128;
    const int nb = blockIdx.y * 128;

    const int fr = tid >> 1;
    const int fk = (tid & 1) * 8;

    const bool kvec = ((Ksrc & 3) == 0);

    const float* apb = A + (size_t)(mb + fr) * Ksrc + fk;
    const float* wpb = W + (size_t)(nb + fr) * Ksrc + fk;

    float c[4][4][4];
#pragma unroll
    for (int i = 0; i < 4; ++i)
#pragma unroll
        for (int j = 0; j < 4; ++j)
#pragma unroll
            for (int q = 0; q < 4; ++q) c[i][j][q] = 0.f;

    float av[8], wv[8];
    if (kvec) {
        float4 a0 = *(const float4*)(apb);
        float4 a1 = *(const float4*)(apb + 4);
        float4 w0 = *(const float4*)(wpb);
        float4 w1 = *(const float4*)(wpb + 4);
        av[0]=a0.x; av[1]=a0.y; av[2]=a0.z; av[3]=a0.w;
        av[4]=a1.x; av[5]=a1.y; av[6]=a1.z; av[7]=a1.w;
        wv[0]=w0.x; wv[1]=w0.y; wv[2]=w0.z; wv[3]=w0.w;
        wv[4]=w1.x; wv[5]=w1.y; wv[6]=w1.z; wv[7]=w1.w;
    } else {
#pragma unroll
        for (int j = 0; j < 8; ++j) {
            bool ok = (fk + j) < Ksrc;
            av[j] = ok ? apb[j] : 0.f;
            wv[j] = ok ? wpb[j] : 0.f;
        }
    }
#pragma unroll
    for (int j = 0; j < 8; ++j) {
        Asb[(fk + j) * TSTR + fr] = tf32_(av[j]);
        Bsb[(fk + j) * TSTR + fr] = tf32_(wv[j]);
    }
    __syncthreads();

    int cur = 0;
    for (int k0 = 0; k0 < Kiter; k0 += 16) {
        const bool more = (k0 + 16) < Kiter;
        if (more) {
            if (kvec) {
                float4 a0 = *(const float4*)(apb + k0 + 16);
                float4 a1 = *(const float4*)(apb + k0 + 20);
                float4 w0 = *(const float4*)(wpb + k0 + 16);
                float4 w1 = *(const float4*)(wpb + k0 + 20);
                av[0]=a0.x; av[1]=a0.y; av[2]=a0.z; av[3]=a0.w;
                av[4]=a1.x; av[5]=a1.y; av[6]=a1.z; av[7]=a1.w;
                wv[0]=w0.x; wv[1]=w0.y; wv[2]=w0.z; wv[3]=w0.w;
                wv[4]=w1.x; wv[5]=w1.y; wv[6]=w1.z; wv[7]=w1.w;
            } else {
#pragma unroll
                for (int j = 0; j < 8; ++j) {
                    bool ok = (k0 + 16 + fk + j) < Ksrc;
                    av[j] = ok ? apb[k0 + 16 + j] : 0.f;
                    wv[j] = ok ? wpb[k0 + 16 + j] : 0.f;
                }
            }
        }

        const unsigned* As = Asb + cur * (16 * TSTR);
        const unsigned* Bs = Bsb + cur * (16 * TSTR);
#pragma unroll
        for (int ks = 0; ks < 2; ++ks) {
            const int kk = ks * 8;
            unsigned bf[4][2];
#pragma unroll
            for (int j = 0; j < 4; ++j) {
                int cb = wn * 32 + j * 8 + g;
                bf[j][0] = Bs[(kk + tg) * TSTR + cb];
                bf[j][1] = Bs[(kk + tg + 4) * TSTR + cb];
            }
#pragma unroll
            for (int i = 0; i < 4; ++i) {
                int rb = wm * 64 + i * 16;
                unsigned af[4];
                af[0] = As[(kk + tg) * TSTR + rb + g];
                af[1] = As[(kk + tg) * TSTR + rb + g + 8];
                af[2] = As[(kk + tg + 4) * TSTR + rb + g];
                af[3] = As[(kk + tg + 4) * TSTR + rb + g + 8];
#pragma unroll
                for (int j = 0; j < 4; ++j)
                    mma_tf32(c[i][j], af, bf[j][0], bf[j][1]);
            }
        }

        if (more) {
            unsigned* An = Asb + (cur ^ 1) * (16 * TSTR);
            unsigned* Bn = Bsb + (cur ^ 1) * (16 * TSTR);
#pragma unroll
            for (int j = 0; j < 8; ++j) {
                An[(fk + j) * TSTR + fr] = tf32_(av[j]);
                Bn[(fk + j) * TSTR + fr] = tf32_(wv[j]);
            }
        }
        __syncthreads();
        cur ^= 1;
    }

#pragma unroll
    for (int j = 0; j < 4; ++j) {
        int col = nb + wn * 32 + j * 8 + 2 * tg;
        float2 bb = *(const float2*)(bias + col);
#pragma unroll
        for (int i = 0; i < 4; ++i) {
            int row = mb + wm * 64 + i * 16 + g;
            float2 v0; v0.x = c[i][j][0] + bb.x; v0.y = c[i][j][1] + bb.y;
            float2 v1; v1.x = c[i][j][2] + bb.x; v1.y = c[i][j][3] + bb.y;
            *(float2*)(C + (size_t)row * N + col)       = v0;
            *(float2*)(C + (size_t)(row + 8) * N + col) = v1;
        }
    }
}

// ---------------------------------------------------------------------------
// GRU recurrence with interleaved h-ownership + pre-barrier own-slice compute.
// 32 clusters x 4 CTAs, 512 threads.  CTA rank owns h-blocks {rank + 4j}*16,
// so each k-half lane owns two 16-k windows of self-produced h — computed
// BEFORE cl_wait, hiding the barrier latency.  Otherwise R14 structure.
// ---------------------------------------------------------------------------
#define RSTR 264
#define REC_W_FLOATS (192 * RSTR)
#define REC_SMEM ((192 * RSTR + 2 * 8 * RSTR) * 4)   // 219648 B

DEV_INLINE unsigned ctarank() { unsigned r; asm("mov.u32 %0, %%cluster_ctarank;" : "=r"(r)); return r; }
DEV_INLINE unsigned s2u(const void* p) {
    unsigned a;
    asm("{ .reg .u64 t; cvta.to.shared.u64 t, %1; cvt.u32.u64 %0, t; }" : "=r"(a) : "l"(p));
    return a;
}
DEV_INLINE unsigned mapa_(unsigned a, unsigned r) {
    unsigned o; asm("mapa.shared::cluster.u32 %0, %1, %2;" : "=r"(o) : "r"(a), "r"(r)); return o;
}
DEV_INLINE void st_cluster_u32(unsigned addr, unsigned v) {
    asm volatile("st.shared::cluster.u32 [%0], %1;" :: "r"(addr), "r"(v) : "memory");
}
DEV_INLINE void cl_arrive() { asm volatile("barrier.cluster.arrive.aligned;" ::: "memory"); }
DEV_INLINE void cl_wait()   { asm volatile("barrier.cluster.wait.aligned;"   ::: "memory"); }

// one k4 chunk of the gate matvec at smem float-offset (o) from the bases
#define REC_CHUNK(o) do {                                                   \
    ulonglong2 wrv = *(const ulonglong2*)(wr + (o));                        \
    ulonglong2 wzv = *(const ulonglong2*)(wz + (o));                        \
    ulonglong2 wnv = *(const ulonglong2*)(wn + (o));                        \
    ulonglong2 h0v = *(const ulonglong2*)(h0r + (o));                       \
    ulonglong2 h1v = *(const ulonglong2*)(h1r + (o));                       \
    ar0 = fma2(wrv.x, h0v.x, ar0); ar0 = fma2(wrv.y, h0v.y, ar0);           \
    az0 = fma2(wzv.x, h0v.x, az0); az0 = fma2(wzv.y, h0v.y, az0);           \
    an0 = fma2(wnv.x, h0v.x, an0); an0 = fma2(wnv.y, h0v.y, an0);           \
    ar1 = fma2(wrv.x, h1v.x, ar1); ar1 = fma2(wrv.y, h1v.y, ar1);           \
    az1 = fma2(wzv.x, h1v.x, az1); az1 = fma2(wzv.y, h1v.y, az1);           \
    an1 = fma2(wnv.x, h1v.x, an1); an1 = fma2(wnv.y, h1v.y, an1);           \
} while (0)

__global__ __launch_bounds__(512, 1) void gru_rec(
    const float* __restrict__ xg, const float* __restrict__ W_hh,
    const float* __restrict__ b_hh, float* __restrict__ out_seq,
    float* __restrict__ hT, int layer0)
{
    extern __shared__ float smem[];
    float* w = smem;                        // [192 rows][264]
    float* hbase = smem + REC_W_FLOATS;     // [2 bufs][8 batches][264]

    const int tid = threadIdx.x;
    const unsigned rank = ctarank();
    const int cid = blockIdx.x >> 2;
    const int h_local = tid >> 3;           // 0..63
    const int bp = (tid >> 1) & 3;
    const int ks = tid & 1;
    // interleaved ownership: CTA rank owns h-blocks {rank + 4j}
    const int h_glob = ((h_local >> 4) * 64) + (int)rank * 16 + (h_local & 15);
    const int bsel = bp + 4 * ks;
    const int bglob = cid * 8 + bsel;
    const int hpoff = h_glob + ((h_glob >= 128) ? 4 : 0);
    const int r16 = (int)rank * 16;         // own-window base within each k-half

    // Load W_hh slice: smem row g*64+hl <- global row g*256 + h_glob(hl)
    for (int i = tid; i < 192 * 64; i += 512) {
        int row = i >> 6, kk = (i & 63) * 4;
        int hl = row & 63;
        int grow = (row >> 6) * 256 + ((hl >> 4) * 64) + (int)rank * 16 + (hl & 15);
        float4 v = ((const float4*)W_hh)[(size_t)grow * 64 + (kk >> 2)];
        *(float4*)(w + row * RSTR + kk + ((kk >= 128) ? 4 : 0)) = v;
    }
    for (int i = tid; i < 8 * RSTR; i += 512) hbase[i] = 0.f;

    const float bh_r = b_hh[h_glob];
    const float bh_z = b_hh[256 + h_glob];
    const float bh_n = b_hh[512 + h_glob];

    __syncthreads();      // seals zeroed own slice for t=0 pre-phase
    cl_arrive();          // gen 0 (consumed by first in-loop wait)

    unsigned hbase_u = s2u(hbase);
    unsigned pb[4];
#pragma unroll
    for (int q = 0; q < 4; ++q) pb[q] = mapa_(hbase_u, (unsigned)q);

    const int ko = ks * 132;
    const float* wr = w + h_local * RSTR + ko;
    const float* wz = wr + 64 * RSTR;
    const float* wn = wr + 128 * RSTR;

    const float* xrow = xg + (size_t)bglob * TT * G3;
    float xr = xrow[h_glob], xz = xrow[256 + h_glob], xn = xrow[512 + h_glob];

    float hp = 0.f;

    int p = 0;
    for (int t = 0; t < TT; ++t) {
        const float* h0r = hbase + (p * 8 + bp) * RSTR + ko;
        const float* h1r = h0r + 4 * RSTR;

        ull ar0 = 0, az0 = 0, an0 = 0, ar1 = 0, az1 = 0, an1 = 0;

        // ---- pre-phase: own-window chunks (self-produced h, already valid) ----
#pragma unroll
        for (int j = 0; j < 4; ++j) {
            REC_CHUNK(r16 + 4 * j);
            REC_CHUNK(r16 + 64 + 4 * j);
        }

        cl_wait();   // seals peers' h broadcasts for this step

        // ---- main phase: remaining chunks of this lane's k-half ----
#pragma unroll 4
        for (int k = 0; k < r16; k += 4) REC_CHUNK(k);
#pragma unroll
        for (int j = 0; j < 12; ++j) REC_CHUNK(r16 + 16 + 4 * j);
#pragma unroll 4
        for (int k = r16 + 80; k < 128; k += 4) REC_CHUNK(k);

        float2 s;
        s = unpk(ar0); float fr0 = s.x + s.y;
        s = unpk(az0); float fz0 = s.x + s.y;
        s = unpk(an0); float fn0 = s.x + s.y;
        s = unpk(ar1); float fr1 = s.x + s.y;
        s = unpk(az1); float fz1 = s.x + s.y;
        s = unpk(an1); float fn1 = s.x + s.y;

        float sr = ks ? fr0 : fr1;
        float sz = ks ? fz0 : fz1;
        float sn = ks ? fn0 : fn1;
        float rr = __shfl_xor_sync(0xffffffffu, sr, 1);
        float rz = __shfl_xor_sync(0xffffffffu, sz, 1);
        float rn = __shfl_xor_sync(0xffffffffu, sn, 1);
        float hr = (ks ? fr1 : fr0) + rr;
        float hz = (ks ? fz1 : fz0) + rz;
        float hn = (ks ? fn1 : fn0) + rn;

        float r = sigm_(xr + bh_r + hr);
        float z = sigm_(xz + bh_z + hz);
        float n = tanh_(xn + r * (hn + bh_n));
        float hnew = (1.f - z) * n + z * hp;
        hp = hnew;

        unsigned off = (unsigned)(((1 - p) * 8 + bsel) * RSTR + hpoff) * 4u;
        unsigned hb = __float_as_uint(hnew);
        st_cluster_u32(pb[0] + off, hb);
        st_cluster_u32(pb[1] + off, hb);
        st_cluster_u32(pb[2] + off, hb);
        st_cluster_u32(pb[3] + off, hb);

        __syncthreads();   // seal own-slice stores for next step's pre-phase
        cl_arrive();       // gen t+1 (release: bcast visible to peers at their wait)

        // off-path work while peer arrivals accumulate
        if (t + 1 < TT) {
            const float* xp = xrow + (size_t)(t + 1) * G3;
            xr = xp[h_glob]; xz = xp[256 + h_glob]; xn = xp[512 + h_glob];
        }
        if (layer0) {
            out_seq[((size_t)bglob * TT + t) * HH + h_glob] = hnew;
        } else if (t == TT - 1) {
            hT[bglob * HH + h_glob] = hnew;
        }

        p ^= 1;
    }

    cl_wait();   // drain final generation — no CTA exits with stores in flight
}

// ---------------------------------------------------------------------------
// Launch helpers
// ---------------------------------------------------------------------------
static void launch_rec(const float* xg, const float* Whh, const float* bhh,
                       float* oseq, float* hT, int layer0)
{
    cudaFuncSetAttribute(gru_rec, cudaFuncAttributeMaxDynamicSharedMemorySize, REC_SMEM);
    cudaLaunchConfig_t cfg = {};
    cfg.gridDim = dim3(128, 1, 1);
    cfg.blockDim = dim3(512, 1, 1);
    cfg.dynamicSmemBytes = REC_SMEM;
    cfg.stream = 0;
    cudaLaunchAttribute at[1];
    at[0].id = cudaLaunchAttributeClusterDimension;
    at[0].val.clusterDim.x = 4;
    at[0].val.clusterDim.y = 1;
    at[0].val.clusterDim.z = 1;
    cfg.attrs = at;
    cfg.numAttrs = 1;
    cudaLaunchKernelEx(&cfg, gru_rec, xg, Whh, bhh, oseq, hT, layer0);
}

static void launch_gemm(const float* A, const float* W, const float* bias,
                        float* C, int M, int N, int Kiter, int Ksrc)
{
    cudaFuncSetAttribute(gemm_tf32, cudaFuncAttributeMaxDynamicSharedMemorySize, GEMM_SMEM);
    gemm_tf32<<<dim3(M / 128, N / 128), 256, GEMM_SMEM>>>(A, W, bias, C, M, N, Kiter, Ksrc);
}

extern "C" void kernel_launch(void* const* d_in, const int* in_sizes, int n_in,
                              void* d_out, int out_size)
{
    const float* x     = (const float*)d_in[0];
    const float* W_ih0 = (const float*)d_in[1];
    const float* W_hh0 = (const float*)d_in[2];
    const float* b_ih0 = (const float*)d_in[3];
    const float* b_hh0 = (const float*)d_in[4];
    const float* W_ih1 = (const float*)d_in[5];
    const float* W_hh1 = (const float*)d_in[6];
    const float* b_ih1 = (const float*)d_in[7];
    const float* b_hh1 = (const float*)d_in[8];
    const float* fc_W  = (const float*)d_in[9];
    const float* fc_b  = (const float*)d_in[10];
    float* out = (float*)d_out;

    float *xg, *o0, *hT;
    cudaGetSymbolAddress((void**)&xg, g_xg);
    cudaGetSymbolAddress((void**)&o0, g_out0);
    cudaGetSymbolAddress((void**)&hT, g_hT);

    const int M = BB * TT;  // 131072

    launch_gemm(x, W_ih0, b_ih0, xg, M, G3, 80, 75);
    launch_rec(xg, W_hh0, b_hh0, o0, nullptr, 1);
    launch_gemm(o0, W_ih1, b_ih1, xg, M, G3, 256, 256);
    launch_rec(xg, W_hh1, b_hh1, nullptr, hT, 0);
    launch_gemm(hT, fc_W, fc_b, out, BB, HH, HH, HH);
}